// round 3
// baseline (speedup 1.0000x reference)
#include <cuda_runtime.h>
#include <cstdint>

#define D 64
#define MAXN 100000

// Scratch (device globals — no allocation allowed)
__device__ float g_agg[MAXN * D];   // (1+eps)*x + sum_agg ; later reused as t2
__device__ float g_t1[MAXN * D];    // output of first Linear
__device__ float g_stats[256];      // sum1[64], sq1[64], sum2[64], sq2[64]

// ---------------------------------------------------------------------------
// K0: agg = (1+eps)*x ; zero stats accumulators
// ---------------------------------------------------------------------------
__global__ __launch_bounds__(256) void k_init(const float* __restrict__ x,
                                              const float* __restrict__ epsp,
                                              float* __restrict__ agg, int n4) {
    int i = blockIdx.x * 256 + threadIdx.x;
    if (blockIdx.x == 0 && threadIdx.x < 256) g_stats[threadIdx.x] = 0.f;
    if (i >= n4) return;
    float s = 1.0f + epsp[0];
    float4 v = ((const float4*)x)[i];
    v.x *= s; v.y *= s; v.z *= s; v.w *= s;
    ((float4*)agg)[i] = v;
}

// ---------------------------------------------------------------------------
// K1: scatter-add  agg[dst] += x[src]   (16 threads per edge, v4 reductions)
// edge_index is INT32
// ---------------------------------------------------------------------------
__global__ __launch_bounds__(256) void k_scatter(const float* __restrict__ x,
                                                 const int* __restrict__ ei,
                                                 float* __restrict__ agg, int E) {
    long long idx = (long long)blockIdx.x * 256 + threadIdx.x;
    long long e = idx >> 4;
    int q = (int)(idx & 15);
    if (e >= E) return;
    int src = ei[e];
    int dst = ei[(long long)E + e];
    float4 v = ((const float4*)x)[(size_t)src * 16 + q];
    float* p = agg + (size_t)dst * 64 + q * 4;
    asm volatile("red.global.add.v4.f32 [%0], {%1, %2, %3, %4};"
                 :: "l"(p), "f"(v.x), "f"(v.y), "f"(v.z), "f"(v.w)
                 : "memory");
}

// ---------------------------------------------------------------------------
// K2/K3: out = [maybe BN+ReLU](in) @ W + b ; accumulate column sum/sumsq
// X tile stored TRANSPOSED in smem: Xs[k][row], stride 68 (16B-aligned, no
// read conflicts). Inner loop: 2x LDS.128 per k for 16 FMAs.
// ---------------------------------------------------------------------------
__global__ __launch_bounds__(256) void k_gemm_bn(
    const float* __restrict__ in, const float* __restrict__ W,
    const float* __restrict__ b, float* __restrict__ out,
    float* __restrict__ statsOut,            // [0..63]=sum, [64..127]=sumsq
    const float* __restrict__ statsIn,       // sum/sq of the *input* (or null)
    const float* __restrict__ gamma, const float* __restrict__ beta,
    int N, int applyBNin)
{
    __shared__ float Xs[64 * 68];   // [k][row] transposed, pad 68
    __shared__ float Ws[64 * 64];   // [k][col] row-major
    __shared__ float Bs[64];
    __shared__ float SC[64];
    __shared__ float SH[64];
    __shared__ float red[16 * 64];

    const int tid = threadIdx.x;
    const int t = tid & 15;       // column group (4 cols)
    const int r = tid >> 4;       // row group (4 rows)
    const int row0 = blockIdx.x * 64;

    // Load W (64x64) and bias
    #pragma unroll
    for (int i = 0; i < 4; i++) {
        int lin = tid + i * 256;
        ((float4*)Ws)[lin] = ((const float4*)W)[lin];
    }
    if (tid < 64) {
        Bs[tid] = b[tid];
        if (applyBNin) {
            float invN = 1.0f / (float)N;
            float mean = statsIn[tid] * invN;
            float var  = statsIn[64 + tid] * invN - mean * mean;
            float sc = gamma[tid] * rsqrtf(var + 1e-5f);
            SC[tid] = sc;
            SH[tid] = beta[tid] - mean * sc;
        }
    }
    __syncthreads();

    // Stage 64 input rows TRANSPOSED. Warp-lane mapping: 32 consecutive rows
    // for one column-quad -> conflict-free STS.32, broadcast SC/SH.
    #pragma unroll
    for (int i = 0; i < 4; i++) {
        int lin = tid + i * 256;
        int row = lin & 63;
        int c4 = lin >> 6;              // 0..15
        float4 v = make_float4(0.f, 0.f, 0.f, 0.f);
        int gr = row0 + row;
        if (gr < N) v = ((const float4*)in)[(size_t)gr * 16 + c4];
        if (applyBNin) {
            int c = c4 * 4;
            v.x = fmaxf(fmaf(v.x, SC[c + 0], SH[c + 0]), 0.f);
            v.y = fmaxf(fmaf(v.y, SC[c + 1], SH[c + 1]), 0.f);
            v.z = fmaxf(fmaf(v.z, SC[c + 2], SH[c + 2]), 0.f);
            v.w = fmaxf(fmaf(v.w, SC[c + 3], SH[c + 3]), 0.f);
        }
        int c = c4 * 4;
        Xs[(c + 0) * 68 + row] = v.x;
        Xs[(c + 1) * 68 + row] = v.y;
        Xs[(c + 2) * 68 + row] = v.z;
        Xs[(c + 3) * 68 + row] = v.w;
    }
    __syncthreads();

    // Register-tiled GEMM: 4 rows x 4 cols per thread, outer-product form.
    float4 a0 = make_float4(0.f,0.f,0.f,0.f);
    float4 a1 = a0, a2 = a0, a3 = a0;
    #pragma unroll
    for (int k = 0; k < 64; k++) {
        float4 xv = *(const float4*)&Xs[k * 68 + r * 4];   // 4 rows at this k
        float4 wv = *(const float4*)&Ws[k * 64 + t * 4];   // 4 cols at this k
        a0.x = fmaf(xv.x, wv.x, a0.x); a0.y = fmaf(xv.x, wv.y, a0.y);
        a0.z = fmaf(xv.x, wv.z, a0.z); a0.w = fmaf(xv.x, wv.w, a0.w);
        a1.x = fmaf(xv.y, wv.x, a1.x); a1.y = fmaf(xv.y, wv.y, a1.y);
        a1.z = fmaf(xv.y, wv.z, a1.z); a1.w = fmaf(xv.y, wv.w, a1.w);
        a2.x = fmaf(xv.z, wv.x, a2.x); a2.y = fmaf(xv.z, wv.y, a2.y);
        a2.z = fmaf(xv.z, wv.z, a2.z); a2.w = fmaf(xv.z, wv.w, a2.w);
        a3.x = fmaf(xv.w, wv.x, a3.x); a3.y = fmaf(xv.w, wv.y, a3.y);
        a3.z = fmaf(xv.w, wv.z, a3.z); a3.w = fmaf(xv.w, wv.w, a3.w);
    }
    float4 bb = *(const float4*)&Bs[t * 4];
    a0.x += bb.x; a0.y += bb.y; a0.z += bb.z; a0.w += bb.w;
    a1.x += bb.x; a1.y += bb.y; a1.z += bb.z; a1.w += bb.w;
    a2.x += bb.x; a2.y += bb.y; a2.z += bb.z; a2.w += bb.w;
    a3.x += bb.x; a3.y += bb.y; a3.z += bb.z; a3.w += bb.w;

    // Store + local stats
    float4 ls = make_float4(0.f,0.f,0.f,0.f);
    float4 lq = ls;
    float4 acc[4] = {a0, a1, a2, a3};
    #pragma unroll
    for (int j = 0; j < 4; j++) {
        int row = row0 + r * 4 + j;
        if (row < N) {
            *(float4*)&out[(size_t)row * 64 + t * 4] = acc[j];
            ls.x += acc[j].x; ls.y += acc[j].y; ls.z += acc[j].z; ls.w += acc[j].w;
            lq.x += acc[j].x * acc[j].x; lq.y += acc[j].y * acc[j].y;
            lq.z += acc[j].z * acc[j].z; lq.w += acc[j].w * acc[j].w;
        }
    }

    // Block reduction of stats, then atomic into global accumulators
    __syncthreads();
    *(float4*)&red[r * 64 + t * 4] = ls;
    __syncthreads();
    if (tid < 64) {
        float s = 0.f;
        #pragma unroll
        for (int rr = 0; rr < 16; rr++) s += red[rr * 64 + tid];
        atomicAdd(&statsOut[tid], s);
    }
    __syncthreads();
    *(float4*)&red[r * 64 + t * 4] = lq;
    __syncthreads();
    if (tid < 64) {
        float s = 0.f;
        #pragma unroll
        for (int rr = 0; rr < 16; rr++) s += red[rr * 64 + tid];
        atomicAdd(&statsOut[64 + tid], s);
    }
}

// ---------------------------------------------------------------------------
// K4: out = x + relu(BN(t2))
// ---------------------------------------------------------------------------
__global__ __launch_bounds__(256) void k_final(const float* __restrict__ x,
                                               const float* __restrict__ t2,
                                               const float* __restrict__ statsIn,
                                               const float* __restrict__ gamma,
                                               const float* __restrict__ beta,
                                               float* __restrict__ out, int N) {
    __shared__ float SC[64];
    __shared__ float SH[64];
    int tid = threadIdx.x;
    if (tid < 64) {
        float invN = 1.0f / (float)N;
        float mean = statsIn[tid] * invN;
        float var  = statsIn[64 + tid] * invN - mean * mean;
        float sc = gamma[tid] * rsqrtf(var + 1e-5f);
        SC[tid] = sc;
        SH[tid] = beta[tid] - mean * sc;
    }
    __syncthreads();
    int n4 = N * 16;
    for (int i = blockIdx.x * 256 + tid; i < n4; i += gridDim.x * 256) {
        int c = (i & 15) * 4;
        float4 v = ((const float4*)t2)[i];
        float4 xv = ((const float4*)x)[i];
        float4 o;
        o.x = xv.x + fmaxf(fmaf(v.x, SC[c + 0], SH[c + 0]), 0.f);
        o.y = xv.y + fmaxf(fmaf(v.y, SC[c + 1], SH[c + 1]), 0.f);
        o.z = xv.z + fmaxf(fmaf(v.z, SC[c + 2], SH[c + 2]), 0.f);
        o.w = xv.w + fmaxf(fmaf(v.w, SC[c + 3], SH[c + 3]), 0.f);
        ((float4*)out)[i] = o;
    }
}

// ---------------------------------------------------------------------------
extern "C" void kernel_launch(void* const* d_in, const int* in_sizes, int n_in,
                              void* d_out, int out_size) {
    const float* x    = (const float*)d_in[0];
    const int*   ei   = (const int*)d_in[1];
    const float* eps  = (const float*)d_in[2];
    const float* W1   = (const float*)d_in[3];
    const float* b1   = (const float*)d_in[4];
    const float* g1   = (const float*)d_in[5];
    const float* beta1= (const float*)d_in[6];
    const float* W2   = (const float*)d_in[7];
    const float* b2   = (const float*)d_in[8];
    const float* gh   = (const float*)d_in[9];
    const float* betah= (const float*)d_in[10];
    float* out = (float*)d_out;

    int N = in_sizes[0] / D;
    int E = in_sizes[1] / 2;
    if (N > MAXN) N = MAXN;

    float* agg;   cudaGetSymbolAddress((void**)&agg, g_agg);
    float* t1;    cudaGetSymbolAddress((void**)&t1, g_t1);
    float* stats; cudaGetSymbolAddress((void**)&stats, g_stats);

    int n4 = N * 16;
    int initBlocks = (n4 + 255) / 256;
    k_init<<<initBlocks, 256>>>(x, eps, agg, n4);

    long long scatterThreads = (long long)E * 16;
    int scatterBlocks = (int)((scatterThreads + 255) / 256);
    k_scatter<<<scatterBlocks, 256>>>(x, ei, agg, E);

    int gemmBlocks = (N + 63) / 64;
    k_gemm_bn<<<gemmBlocks, 256>>>(agg, W1, b1, t1, stats, nullptr, nullptr, nullptr, N, 0);
    k_gemm_bn<<<gemmBlocks, 256>>>(t1, W2, b2, agg, stats + 128, stats, g1, beta1, N, 1);
    k_final<<<initBlocks, 256>>>(x, agg, stats + 128, gh, betah, out, N);
}

// round 4
// speedup vs baseline: 1.2474x; 1.2474x over previous
#include <cuda_runtime.h>
#include <cstdint>

#define D 64
#define MAXN 100000
#define MAXE 1600000
#define SCAN_BLK 1024

// Scratch (device globals — no allocation allowed)
__device__ float g_agg[MAXN * D];      // agg result; later reused as t2
__device__ float g_t1[MAXN * D];       // output of first Linear
__device__ float g_stats[256];         // sum1[64], sq1[64], sum2[64], sq2[64]
__device__ int   g_cnt[MAXN + SCAN_BLK];     // degree per node (padded)
__device__ int   g_start[MAXN + 1];          // CSR offsets
__device__ int   g_cursor[MAXN];             // fill cursors
__device__ int   g_srcs[MAXE];               // src grouped by dst
__device__ int   g_bsum[SCAN_BLK];           // per-block sums for scan

// ---------------------------------------------------------------------------
// K_a: zero stats + degree counters
// ---------------------------------------------------------------------------
__global__ __launch_bounds__(256) void k_zero(int N) {
    int i = blockIdx.x * 256 + threadIdx.x;
    if (i < 256) g_stats[i] = 0.f;
    if (i < N + SCAN_BLK) g_cnt[i] = 0;
}

// ---------------------------------------------------------------------------
// K_hist: degree histogram over dst
// ---------------------------------------------------------------------------
__global__ __launch_bounds__(256) void k_hist(const int* __restrict__ ei, int E) {
    int e = blockIdx.x * 256 + threadIdx.x;
    if (e >= E) return;
    int dst = ei[E + e];
    atomicAdd(&g_cnt[dst], 1);
}

// ---------------------------------------------------------------------------
// Scan step 1: per-block sums of g_cnt
// ---------------------------------------------------------------------------
__global__ __launch_bounds__(SCAN_BLK) void k_scan1(int N) {
    __shared__ int sm[SCAN_BLK];
    int t = threadIdx.x;
    int gi = blockIdx.x * SCAN_BLK + t;
    int v = (gi < N) ? g_cnt[gi] : 0;
    sm[t] = v;
    __syncthreads();
    #pragma unroll
    for (int o = 1; o < SCAN_BLK; o <<= 1) {
        int u = (t >= o) ? sm[t - o] : 0;
        __syncthreads();
        sm[t] += u;
        __syncthreads();
    }
    if (t == SCAN_BLK - 1) g_bsum[blockIdx.x] = sm[t];
}

// ---------------------------------------------------------------------------
// Scan step 2: exclusive scan of block sums (single block)
// ---------------------------------------------------------------------------
__global__ __launch_bounds__(SCAN_BLK) void k_scan2(int nb) {
    __shared__ int sm[SCAN_BLK];
    int t = threadIdx.x;
    int v = (t < nb) ? g_bsum[t] : 0;
    sm[t] = v;
    __syncthreads();
    #pragma unroll
    for (int o = 1; o < SCAN_BLK; o <<= 1) {
        int u = (t >= o) ? sm[t - o] : 0;
        __syncthreads();
        sm[t] += u;
        __syncthreads();
    }
    if (t < nb) g_bsum[t] = sm[t] - v;   // exclusive
}

// ---------------------------------------------------------------------------
// Scan step 3: start[i] = exclusive scan; init cursor; start[N]=E
// ---------------------------------------------------------------------------
__global__ __launch_bounds__(SCAN_BLK) void k_scan3(int N) {
    __shared__ int sm[SCAN_BLK];
    int t = threadIdx.x;
    int gi = blockIdx.x * SCAN_BLK + t;
    int v = (gi < N) ? g_cnt[gi] : 0;
    sm[t] = v;
    __syncthreads();
    #pragma unroll
    for (int o = 1; o < SCAN_BLK; o <<= 1) {
        int u = (t >= o) ? sm[t - o] : 0;
        __syncthreads();
        sm[t] += u;
        __syncthreads();
    }
    int base = g_bsum[blockIdx.x];
    if (gi < N) {
        int st = base + sm[t] - v;       // exclusive
        g_start[gi] = st;
        g_cursor[gi] = st;
        if (gi == N - 1) g_start[N] = base + sm[t];
    }
}

// ---------------------------------------------------------------------------
// K_fill: group src by dst
// ---------------------------------------------------------------------------
__global__ __launch_bounds__(256) void k_fill(const int* __restrict__ ei, int E) {
    int e = blockIdx.x * 256 + threadIdx.x;
    if (e >= E) return;
    int src = ei[e];
    int dst = ei[E + e];
    int pos = atomicAdd(&g_cursor[dst], 1);
    g_srcs[pos] = src;
}

// ---------------------------------------------------------------------------
// K_agg: agg[i] = (1+eps)*x[i] + sum over grouped srcs. 16 threads per node.
// ---------------------------------------------------------------------------
__global__ __launch_bounds__(256) void k_agg(const float* __restrict__ x,
                                             const float* __restrict__ epsp,
                                             float* __restrict__ agg, int N) {
    int tid = threadIdx.x;
    int i = blockIdx.x * 16 + (tid >> 4);
    int q = tid & 15;
    if (i >= N) return;
    float s = 1.0f + epsp[0];
    float4 xv = ((const float4*)x)[(size_t)i * 16 + q];
    float4 acc = make_float4(xv.x * s, xv.y * s, xv.z * s, xv.w * s);
    int b = g_start[i];
    int e2 = g_start[i + 1];
    for (int j = b; j < e2; j++) {
        int src = g_srcs[j];
        float4 v = ((const float4*)x)[(size_t)src * 16 + q];
        acc.x += v.x; acc.y += v.y; acc.z += v.z; acc.w += v.w;
    }
    ((float4*)agg)[(size_t)i * 16 + q] = acc;
}

// ---------------------------------------------------------------------------
// GEMM + BN stats (exact R2 version — known 30.4us)
// ---------------------------------------------------------------------------
__global__ __launch_bounds__(256) void k_gemm_bn(
    const float* __restrict__ in, const float* __restrict__ W,
    const float* __restrict__ b, float* __restrict__ out,
    float* __restrict__ statsOut,
    const float* __restrict__ statsIn,
    const float* __restrict__ gamma, const float* __restrict__ beta,
    int N, int applyBNin)
{
    __shared__ float Xs[64 * 68];
    __shared__ float Ws[64 * 64];
    __shared__ float Bs[64];
    __shared__ float SC[64];
    __shared__ float SH[64];
    __shared__ float red[16 * 64];

    const int tid = threadIdx.x;
    const int t = tid & 15;
    const int r = tid >> 4;
    const int row0 = blockIdx.x * 64;

    #pragma unroll
    for (int i = 0; i < 4; i++) {
        int lin = tid + i * 256;
        ((float4*)Ws)[lin] = ((const float4*)W)[lin];
    }
    if (tid < 64) {
        Bs[tid] = b[tid];
        if (applyBNin) {
            float invN = 1.0f / (float)N;
            float mean = statsIn[tid] * invN;
            float var  = statsIn[64 + tid] * invN - mean * mean;
            float sc = gamma[tid] * rsqrtf(var + 1e-5f);
            SC[tid] = sc;
            SH[tid] = beta[tid] - mean * sc;
        }
    }
    __syncthreads();

    #pragma unroll
    for (int i = 0; i < 4; i++) {
        int lin = tid + i * 256;
        int row = lin >> 4;
        int c4 = lin & 15;
        float4 v = make_float4(0.f, 0.f, 0.f, 0.f);
        int gr = row0 + row;
        if (gr < N) v = ((const float4*)in)[(size_t)gr * 16 + c4];
        if (applyBNin) {
            int c = c4 * 4;
            v.x = fmaxf(fmaf(v.x, SC[c + 0], SH[c + 0]), 0.f);
            v.y = fmaxf(fmaf(v.y, SC[c + 1], SH[c + 1]), 0.f);
            v.z = fmaxf(fmaf(v.z, SC[c + 2], SH[c + 2]), 0.f);
            v.w = fmaxf(fmaf(v.w, SC[c + 3], SH[c + 3]), 0.f);
        }
        *(float4*)&Xs[row * 68 + c4 * 4] = v;
    }
    __syncthreads();

    float4 a0 = make_float4(0.f,0.f,0.f,0.f);
    float4 a1 = a0, a2 = a0, a3 = a0;
    const int xb = (r * 4) * 68;
    #pragma unroll
    for (int k = 0; k < 64; k++) {
        float4 w = *(const float4*)&Ws[k * 64 + t * 4];
        float x0 = Xs[xb + k];
        float x1 = Xs[xb + 68 + k];
        float x2 = Xs[xb + 136 + k];
        float x3 = Xs[xb + 204 + k];
        a0.x = fmaf(x0, w.x, a0.x); a0.y = fmaf(x0, w.y, a0.y);
        a0.z = fmaf(x0, w.z, a0.z); a0.w = fmaf(x0, w.w, a0.w);
        a1.x = fmaf(x1, w.x, a1.x); a1.y = fmaf(x1, w.y, a1.y);
        a1.z = fmaf(x1, w.z, a1.z); a1.w = fmaf(x1, w.w, a1.w);
        a2.x = fmaf(x2, w.x, a2.x); a2.y = fmaf(x2, w.y, a2.y);
        a2.z = fmaf(x2, w.z, a2.z); a2.w = fmaf(x2, w.w, a2.w);
        a3.x = fmaf(x3, w.x, a3.x); a3.y = fmaf(x3, w.y, a3.y);
        a3.z = fmaf(x3, w.z, a3.z); a3.w = fmaf(x3, w.w, a3.w);
    }
    float4 bb = *(const float4*)&Bs[t * 4];
    a0.x += bb.x; a0.y += bb.y; a0.z += bb.z; a0.w += bb.w;
    a1.x += bb.x; a1.y += bb.y; a1.z += bb.z; a1.w += bb.w;
    a2.x += bb.x; a2.y += bb.y; a2.z += bb.z; a2.w += bb.w;
    a3.x += bb.x; a3.y += bb.y; a3.z += bb.z; a3.w += bb.w;

    float4 ls = make_float4(0.f,0.f,0.f,0.f);
    float4 lq = ls;
    float4 acc[4] = {a0, a1, a2, a3};
    #pragma unroll
    for (int j = 0; j < 4; j++) {
        int row = row0 + r * 4 + j;
        if (row < N) {
            *(float4*)&out[(size_t)row * 64 + t * 4] = acc[j];
            ls.x += acc[j].x; ls.y += acc[j].y; ls.z += acc[j].z; ls.w += acc[j].w;
            lq.x += acc[j].x * acc[j].x; lq.y += acc[j].y * acc[j].y;
            lq.z += acc[j].z * acc[j].z; lq.w += acc[j].w * acc[j].w;
        }
    }

    __syncthreads();
    *(float4*)&red[r * 64 + t * 4] = ls;
    __syncthreads();
    if (tid < 64) {
        float s = 0.f;
        #pragma unroll
        for (int rr = 0; rr < 16; rr++) s += red[rr * 64 + tid];
        atomicAdd(&statsOut[tid], s);
    }
    __syncthreads();
    *(float4*)&red[r * 64 + t * 4] = lq;
    __syncthreads();
    if (tid < 64) {
        float s = 0.f;
        #pragma unroll
        for (int rr = 0; rr < 16; rr++) s += red[rr * 64 + tid];
        atomicAdd(&statsOut[64 + tid], s);
    }
}

// ---------------------------------------------------------------------------
// K_final: out = x + relu(BN(t2))
// ---------------------------------------------------------------------------
__global__ __launch_bounds__(256) void k_final(const float* __restrict__ x,
                                               const float* __restrict__ t2,
                                               const float* __restrict__ statsIn,
                                               const float* __restrict__ gamma,
                                               const float* __restrict__ beta,
                                               float* __restrict__ out, int N) {
    __shared__ float SC[64];
    __shared__ float SH[64];
    int tid = threadIdx.x;
    if (tid < 64) {
        float invN = 1.0f / (float)N;
        float mean = statsIn[tid] * invN;
        float var  = statsIn[64 + tid] * invN - mean * mean;
        float sc = gamma[tid] * rsqrtf(var + 1e-5f);
        SC[tid] = sc;
        SH[tid] = beta[tid] - mean * sc;
    }
    __syncthreads();
    int n4 = N * 16;
    for (int i = blockIdx.x * 256 + tid; i < n4; i += gridDim.x * 256) {
        int c = (i & 15) * 4;
        float4 v = ((const float4*)t2)[i];
        float4 xv = ((const float4*)x)[i];
        float4 o;
        o.x = xv.x + fmaxf(fmaf(v.x, SC[c + 0], SH[c + 0]), 0.f);
        o.y = xv.y + fmaxf(fmaf(v.y, SC[c + 1], SH[c + 1]), 0.f);
        o.z = xv.z + fmaxf(fmaf(v.z, SC[c + 2], SH[c + 2]), 0.f);
        o.w = xv.w + fmaxf(fmaf(v.w, SC[c + 3], SH[c + 3]), 0.f);
        ((float4*)out)[i] = o;
    }
}

// ---------------------------------------------------------------------------
extern "C" void kernel_launch(void* const* d_in, const int* in_sizes, int n_in,
                              void* d_out, int out_size) {
    const float* x    = (const float*)d_in[0];
    const int*   ei   = (const int*)d_in[1];      // int32
    const float* eps  = (const float*)d_in[2];
    const float* W1   = (const float*)d_in[3];
    const float* b1   = (const float*)d_in[4];
    const float* g1   = (const float*)d_in[5];
    const float* beta1= (const float*)d_in[6];
    const float* W2   = (const float*)d_in[7];
    const float* b2   = (const float*)d_in[8];
    const float* gh   = (const float*)d_in[9];
    const float* betah= (const float*)d_in[10];
    float* out = (float*)d_out;

    int N = in_sizes[0] / D;
    int E = in_sizes[1] / 2;
    if (N > MAXN) N = MAXN;
    if (E > MAXE) E = MAXE;

    float* agg;   cudaGetSymbolAddress((void**)&agg, g_agg);
    float* t1;    cudaGetSymbolAddress((void**)&t1, g_t1);
    float* stats; cudaGetSymbolAddress((void**)&stats, g_stats);

    int eBlocks = (E + 255) / 256;
    int nScanBlocks = (N + SCAN_BLK - 1) / SCAN_BLK;

    k_zero<<<(N + SCAN_BLK + 255) / 256, 256>>>(N);
    k_hist<<<eBlocks, 256>>>(ei, E);
    k_scan1<<<nScanBlocks, SCAN_BLK>>>(N);
    k_scan2<<<1, SCAN_BLK>>>(nScanBlocks);
    k_scan3<<<nScanBlocks, SCAN_BLK>>>(N);
    k_fill<<<eBlocks, 256>>>(ei, E);
    k_agg<<<(N + 15) / 16, 256>>>(x, eps, agg, N);

    int gemmBlocks = (N + 63) / 64;
    k_gemm_bn<<<gemmBlocks, 256>>>(agg, W1, b1, t1, stats, nullptr, nullptr, nullptr, N, 0);
    k_gemm_bn<<<gemmBlocks, 256>>>(t1, W2, b2, agg, stats + 128, stats, g1, beta1, N, 1);

    k_final<<<(N * 16 + 255) / 256, 256>>>(x, agg, stats + 128, gh, betah, out, N);
}

// round 5
// speedup vs baseline: 1.2671x; 1.0158x over previous
#include <cuda_runtime.h>
#include <cuda_fp16.h>
#include <cstdint>

#define D 64
#define MAXN 100000
#define MAXE 1600000
#define SCAN_BLK 1024

// Scratch (device globals — no allocation allowed)
__device__ float g_agg[MAXN * D];      // agg result; later reused as t2
__device__ float g_t1[MAXN * D];       // output of first Linear
__device__ float g_stats[256];         // sum1[64], sq1[64], sum2[64], sq2[64]
__device__ uint2 g_xh[MAXN * 16];      // x staged as fp16 (64 halfs/row = 16 uint2)
__device__ int   g_cnt[MAXN + SCAN_BLK];   // degree per node -> local inclusive scan
__device__ int   g_start[MAXN + 1];        // CSR offsets (local exclusive -> global)
__device__ int   g_cursor[MAXN];           // fill cursors
__device__ int   g_srcs[MAXE];             // src grouped by dst
__device__ int   g_bsum[SCAN_BLK];         // per-block sums for scan

// ---------------------------------------------------------------------------
// K_prep: stage x as fp16, zero stats + degree counters, set g_start[N]=E
// ---------------------------------------------------------------------------
__global__ __launch_bounds__(256) void k_prep(const float* __restrict__ x,
                                              int N, int E) {
    int i = blockIdx.x * 256 + threadIdx.x;
    if (i < 256) g_stats[i] = 0.f;
    if (i < N + SCAN_BLK) g_cnt[i] = 0;
    if (i == 0) g_start[N] = E;
    int n4 = N * 16;
    if (i >= n4) return;
    float4 v = ((const float4*)x)[i];
    __half2 h0 = __floats2half2_rn(v.x, v.y);
    __half2 h1 = __floats2half2_rn(v.z, v.w);
    uint2 u;
    u.x = *(unsigned*)&h0;
    u.y = *(unsigned*)&h1;
    g_xh[i] = u;
}

// ---------------------------------------------------------------------------
// K_hist: degree histogram over dst
// ---------------------------------------------------------------------------
__global__ __launch_bounds__(256) void k_hist(const int* __restrict__ ei, int E) {
    int e = blockIdx.x * 256 + threadIdx.x;
    if (e >= E) return;
    atomicAdd(&g_cnt[ei[E + e]], 1);
}

// ---------------------------------------------------------------------------
// Warp-shuffle block scan helper (1024 threads). Returns inclusive scan of v;
// block total in *total.
// ---------------------------------------------------------------------------
__device__ __forceinline__ int block_scan_1024(int v, int* warpsum, int* total) {
    int lane = threadIdx.x & 31, wid = threadIdx.x >> 5;
    int inc = v;
    #pragma unroll
    for (int o = 1; o < 32; o <<= 1) {
        int u = __shfl_up_sync(0xFFFFFFFFu, inc, o);
        if (lane >= o) inc += u;
    }
    if (lane == 31) warpsum[wid] = inc;
    __syncthreads();
    if (wid == 0) {
        int w = warpsum[lane];
        #pragma unroll
        for (int o = 1; o < 32; o <<= 1) {
            int u = __shfl_up_sync(0xFFFFFFFFu, w, o);
            if (lane >= o) w += u;
        }
        warpsum[lane] = w;
    }
    __syncthreads();
    int base = (wid > 0) ? warpsum[wid - 1] : 0;
    *total = warpsum[31];
    return inc + base;
}

// ---------------------------------------------------------------------------
// Scan1: per-block scan of degrees. g_start <- local exclusive,
// g_cnt <- local inclusive, g_bsum[b] <- block total.
// ---------------------------------------------------------------------------
__global__ __launch_bounds__(SCAN_BLK) void k_scan1(int N) {
    __shared__ int warpsum[32];
    int gi = blockIdx.x * SCAN_BLK + threadIdx.x;
    int v = (gi < N) ? g_cnt[gi] : 0;
    int total;
    int incl = block_scan_1024(v, warpsum, &total);
    if (gi < N) {
        g_cnt[gi] = incl;
        g_start[gi] = incl - v;
    }
    if (threadIdx.x == SCAN_BLK - 1) g_bsum[blockIdx.x] = total;
}

// ---------------------------------------------------------------------------
// Scan2: exclusive scan of block sums (single block, up to 1024 blocks)
// ---------------------------------------------------------------------------
__global__ __launch_bounds__(SCAN_BLK) void k_scan2(int nb) {
    __shared__ int warpsum[32];
    int t = threadIdx.x;
    int v = (t < nb) ? g_bsum[t] : 0;
    int total;
    int incl = block_scan_1024(v, warpsum, &total);
    if (t < nb) g_bsum[t] = incl - v;
}

// ---------------------------------------------------------------------------
// Scan3 (elementwise): add block base, init cursors
// ---------------------------------------------------------------------------
__global__ __launch_bounds__(256) void k_scan3(int N) {
    int gi = blockIdx.x * 256 + threadIdx.x;
    if (gi >= N) return;
    int base = g_bsum[gi / SCAN_BLK];
    int st = g_start[gi] + base;
    g_start[gi] = st;
    g_cursor[gi] = st;
}

// ---------------------------------------------------------------------------
// K_fill: group src by dst
// ---------------------------------------------------------------------------
__global__ __launch_bounds__(256) void k_fill(const int* __restrict__ ei, int E) {
    int e = blockIdx.x * 256 + threadIdx.x;
    if (e >= E) return;
    int src = ei[e];
    int dst = ei[E + e];
    int pos = atomicAdd(&g_cursor[dst], 1);
    g_srcs[pos] = src;
}

// ---------------------------------------------------------------------------
// K_agg: agg[i] = (1+eps)*x[i](fp32) + sum over fp16-staged neighbor rows.
// 16 threads per node; each thread owns 4 columns (one uint2 of 4 halfs).
// ---------------------------------------------------------------------------
__global__ __launch_bounds__(256) void k_agg(const float* __restrict__ x,
                                             const float* __restrict__ epsp,
                                             float* __restrict__ agg, int N) {
    int tid = threadIdx.x;
    int i = blockIdx.x * 16 + (tid >> 4);
    int q = tid & 15;
    if (i >= N) return;
    float s = 1.0f + epsp[0];
    float4 xv = ((const float4*)x)[(size_t)i * 16 + q];
    float4 acc = make_float4(xv.x * s, xv.y * s, xv.z * s, xv.w * s);
    int b = g_start[i];
    int e2 = g_start[i + 1];
    for (int j = b; j < e2; j++) {
        int src = g_srcs[j];
        uint2 u = g_xh[(size_t)src * 16 + q];
        __half2 h0 = *(__half2*)&u.x;
        __half2 h1 = *(__half2*)&u.y;
        float2 f0 = __half22float2(h0);
        float2 f1 = __half22float2(h1);
        acc.x += f0.x; acc.y += f0.y; acc.z += f1.x; acc.w += f1.y;
    }
    ((float4*)agg)[(size_t)i * 16 + q] = acc;
}

// ---------------------------------------------------------------------------
// GEMM + BN stats (R2 version — known 30.4us)
// ---------------------------------------------------------------------------
__global__ __launch_bounds__(256) void k_gemm_bn(
    const float* __restrict__ in, const float* __restrict__ W,
    const float* __restrict__ b, float* __restrict__ out,
    float* __restrict__ statsOut,
    const float* __restrict__ statsIn,
    const float* __restrict__ gamma, const float* __restrict__ beta,
    int N, int applyBNin)
{
    __shared__ float Xs[64 * 68];
    __shared__ float Ws[64 * 64];
    __shared__ float Bs[64];
    __shared__ float SC[64];
    __shared__ float SH[64];
    __shared__ float red[16 * 64];

    const int tid = threadIdx.x;
    const int t = tid & 15;
    const int r = tid >> 4;
    const int row0 = blockIdx.x * 64;

    #pragma unroll
    for (int i = 0; i < 4; i++) {
        int lin = tid + i * 256;
        ((float4*)Ws)[lin] = ((const float4*)W)[lin];
    }
    if (tid < 64) {
        Bs[tid] = b[tid];
        if (applyBNin) {
            float invN = 1.0f / (float)N;
            float mean = statsIn[tid] * invN;
            float var  = statsIn[64 + tid] * invN - mean * mean;
            float sc = gamma[tid] * rsqrtf(var + 1e-5f);
            SC[tid] = sc;
            SH[tid] = beta[tid] - mean * sc;
        }
    }
    __syncthreads();

    #pragma unroll
    for (int i = 0; i < 4; i++) {
        int lin = tid + i * 256;
        int row = lin >> 4;
        int c4 = lin & 15;
        float4 v = make_float4(0.f, 0.f, 0.f, 0.f);
        int gr = row0 + row;
        if (gr < N) v = ((const float4*)in)[(size_t)gr * 16 + c4];
        if (applyBNin) {
            int c = c4 * 4;
            v.x = fmaxf(fmaf(v.x, SC[c + 0], SH[c + 0]), 0.f);
            v.y = fmaxf(fmaf(v.y, SC[c + 1], SH[c + 1]), 0.f);
            v.z = fmaxf(fmaf(v.z, SC[c + 2], SH[c + 2]), 0.f);
            v.w = fmaxf(fmaf(v.w, SC[c + 3], SH[c + 3]), 0.f);
        }
        *(float4*)&Xs[row * 68 + c4 * 4] = v;
    }
    __syncthreads();

    float4 a0 = make_float4(0.f,0.f,0.f,0.f);
    float4 a1 = a0, a2 = a0, a3 = a0;
    const int xb = (r * 4) * 68;
    #pragma unroll
    for (int k = 0; k < 64; k++) {
        float4 w = *(const float4*)&Ws[k * 64 + t * 4];
        float x0 = Xs[xb + k];
        float x1 = Xs[xb + 68 + k];
        float x2 = Xs[xb + 136 + k];
        float x3 = Xs[xb + 204 + k];
        a0.x = fmaf(x0, w.x, a0.x); a0.y = fmaf(x0, w.y, a0.y);
        a0.z = fmaf(x0, w.z, a0.z); a0.w = fmaf(x0, w.w, a0.w);
        a1.x = fmaf(x1, w.x, a1.x); a1.y = fmaf(x1, w.y, a1.y);
        a1.z = fmaf(x1, w.z, a1.z); a1.w = fmaf(x1, w.w, a1.w);
        a2.x = fmaf(x2, w.x, a2.x); a2.y = fmaf(x2, w.y, a2.y);
        a2.z = fmaf(x2, w.z, a2.z); a2.w = fmaf(x2, w.w, a2.w);
        a3.x = fmaf(x3, w.x, a3.x); a3.y = fmaf(x3, w.y, a3.y);
        a3.z = fmaf(x3, w.z, a3.z); a3.w = fmaf(x3, w.w, a3.w);
    }
    float4 bb = *(const float4*)&Bs[t * 4];
    a0.x += bb.x; a0.y += bb.y; a0.z += bb.z; a0.w += bb.w;
    a1.x += bb.x; a1.y += bb.y; a1.z += bb.z; a1.w += bb.w;
    a2.x += bb.x; a2.y += bb.y; a2.z += bb.z; a2.w += bb.w;
    a3.x += bb.x; a3.y += bb.y; a3.z += bb.z; a3.w += bb.w;

    float4 ls = make_float4(0.f,0.f,0.f,0.f);
    float4 lq = ls;
    float4 acc[4] = {a0, a1, a2, a3};
    #pragma unroll
    for (int j = 0; j < 4; j++) {
        int row = row0 + r * 4 + j;
        if (row < N) {
            *(float4*)&out[(size_t)row * 64 + t * 4] = acc[j];
            ls.x += acc[j].x; ls.y += acc[j].y; ls.z += acc[j].z; ls.w += acc[j].w;
            lq.x += acc[j].x * acc[j].x; lq.y += acc[j].y * acc[j].y;
            lq.z += acc[j].z * acc[j].z; lq.w += acc[j].w * acc[j].w;
        }
    }

    __syncthreads();
    *(float4*)&red[r * 64 + t * 4] = ls;
    __syncthreads();
    if (tid < 64) {
        float s = 0.f;
        #pragma unroll
        for (int rr = 0; rr < 16; rr++) s += red[rr * 64 + tid];
        atomicAdd(&statsOut[tid], s);
    }
    __syncthreads();
    *(float4*)&red[r * 64 + t * 4] = lq;
    __syncthreads();
    if (tid < 64) {
        float s = 0.f;
        #pragma unroll
        for (int rr = 0; rr < 16; rr++) s += red[rr * 64 + tid];
        atomicAdd(&statsOut[64 + tid], s);
    }
}

// ---------------------------------------------------------------------------
// K_final: out = x + relu(BN(t2))
// ---------------------------------------------------------------------------
__global__ __launch_bounds__(256) void k_final(const float* __restrict__ x,
                                               const float* __restrict__ t2,
                                               const float* __restrict__ statsIn,
                                               const float* __restrict__ gamma,
                                               const float* __restrict__ beta,
                                               float* __restrict__ out, int N) {
    __shared__ float SC[64];
    __shared__ float SH[64];
    int tid = threadIdx.x;
    if (tid < 64) {
        float invN = 1.0f / (float)N;
        float mean = statsIn[tid] * invN;
        float var  = statsIn[64 + tid] * invN - mean * mean;
        float sc = gamma[tid] * rsqrtf(var + 1e-5f);
        SC[tid] = sc;
        SH[tid] = beta[tid] - mean * sc;
    }
    __syncthreads();
    int n4 = N * 16;
    for (int i = blockIdx.x * 256 + tid; i < n4; i += gridDim.x * 256) {
        int c = (i & 15) * 4;
        float4 v = ((const float4*)t2)[i];
        float4 xv = ((const float4*)x)[i];
        float4 o;
        o.x = xv.x + fmaxf(fmaf(v.x, SC[c + 0], SH[c + 0]), 0.f);
        o.y = xv.y + fmaxf(fmaf(v.y, SC[c + 1], SH[c + 1]), 0.f);
        o.z = xv.z + fmaxf(fmaf(v.z, SC[c + 2], SH[c + 2]), 0.f);
        o.w = xv.w + fmaxf(fmaf(v.w, SC[c + 3], SH[c + 3]), 0.f);
        ((float4*)out)[i] = o;
    }
}

// ---------------------------------------------------------------------------
extern "C" void kernel_launch(void* const* d_in, const int* in_sizes, int n_in,
                              void* d_out, int out_size) {
    const float* x    = (const float*)d_in[0];
    const int*   ei   = (const int*)d_in[1];      // int32
    const float* eps  = (const float*)d_in[2];
    const float* W1   = (const float*)d_in[3];
    const float* b1   = (const float*)d_in[4];
    const float* g1   = (const float*)d_in[5];
    const float* beta1= (const float*)d_in[6];
    const float* W2   = (const float*)d_in[7];
    const float* b2   = (const float*)d_in[8];
    const float* gh   = (const float*)d_in[9];
    const float* betah= (const float*)d_in[10];
    float* out = (float*)d_out;

    int N = in_sizes[0] / D;
    int E = in_sizes[1] / 2;
    if (N > MAXN) N = MAXN;
    if (E > MAXE) E = MAXE;

    float* agg;   cudaGetSymbolAddress((void**)&agg, g_agg);
    float* t1;    cudaGetSymbolAddress((void**)&t1, g_t1);
    float* stats; cudaGetSymbolAddress((void**)&stats, g_stats);

    int eBlocks = (E + 255) / 256;
    int nScanBlocks = (N + SCAN_BLK - 1) / SCAN_BLK;

    k_prep<<<(N * 16 + 255) / 256, 256>>>(x, N, E);
    k_hist<<<eBlocks, 256>>>(ei, E);
    k_scan1<<<nScanBlocks, SCAN_BLK>>>(N);
    k_scan2<<<1, SCAN_BLK>>>(nScanBlocks);
    k_scan3<<<(N + 255) / 256, 256>>>(N);
    k_fill<<<eBlocks, 256>>>(ei, E);
    k_agg<<<(N + 15) / 16, 256>>>(x, eps, agg, N);

    int gemmBlocks = (N + 63) / 64;
    k_gemm_bn<<<gemmBlocks, 256>>>(agg, W1, b1, t1, stats, nullptr, nullptr, nullptr, N, 0);
    k_gemm_bn<<<gemmBlocks, 256>>>(t1, W2, b2, agg, stats + 128, stats, g1, beta1, N, 1);

    k_final<<<(N * 16 + 255) / 256, 256>>>(x, agg, stats + 128, gh, betah, out, N);
}